// round 16
// baseline (speedup 1.0000x reference)
#include <cuda_runtime.h>
#include <stdint.h>

// Problem shape (fixed for this problem instance)
#define Bn 8
#define Hn 12
#define Sn 1024
#define Dn 64
#define BHn (Bn*Hn)

#define QT 32            // query rows per block
#define KT 128           // k columns per score tile
#define NKT (Sn/KT)      // 8
#define NTHREADS 256

#define QPAD 40          // padded stride for transposed Q tile (mult of 4 words)
#define KPAD 136         // padded stride for transposed K tile (mult of 4 words)

#define SMEM_S_FLOATS   (QT*Sn)                 // 32768
#define SMEM_Q_FLOATS   (Dn*QPAD)               // 2560
#define SMEM_KV_FLOATS  ((Dn*KPAD > KT*Dn) ? (Dn*KPAD) : (KT*Dn))  // 8704
#define SMEM_TOTAL_FLOATS (SMEM_S_FLOATS + SMEM_Q_FLOATS + SMEM_KV_FLOATS + QT)
#define SMEM_BYTES (SMEM_TOTAL_FLOATS * 4)

// mask dtype classification result: 0=int32, 1=uint8/bool, 2=float32, 3=bfloat16
__device__ int g_mask_kind;

__global__ void detect_mask_kind_kernel(const unsigned int* __restrict__ mw) {
    int oi = 1, ou = 1, of = 1, ob = 1;
#pragma unroll
    for (int i = 0; i < 4; i++) {
        unsigned x = mw[threadIdx.x + i * 256];
        oi &= (x <= 1u);                                   // int32 words 0/1
        ou &= ((x & 0xFEFEFEFEu) == 0u);                   // every byte 0/1
        of &= (x == 0u || x == 0x3F800000u);               // fp32 0.0/1.0
        unsigned lo = x & 0xFFFFu, hi = x >> 16;
        ob &= ((lo == 0u || lo == 0x3F80u) && (hi == 0u || hi == 0x3F80u)); // bf16
    }
    oi = __syncthreads_and(oi);
    ou = __syncthreads_and(ou);
    of = __syncthreads_and(of);
    ob = __syncthreads_and(ob);
    if (threadIdx.x == 0)
        g_mask_kind = oi ? 0 : (ou ? 1 : (of ? 2 : (ob ? 3 : 1)));
}

__global__ __launch_bounds__(NTHREADS, 1)
void sdpa_fused_kernel(const float* __restrict__ Q,
                       const float* __restrict__ K,
                       const float* __restrict__ V,
                       const void*  __restrict__ mask,
                       float* __restrict__ ctx_out,
                       float* __restrict__ attn_out)
{
    extern __shared__ float sm[];
    float* sS   = sm;                         // [QT][Sn] scores / exp values
    float* sQt  = sS  + SMEM_S_FLOATS;        // [Dn][QPAD] transposed Q tile
    float* sKV  = sQt + SMEM_Q_FLOATS;        // K tile transposed / V tile natural
    float* sInv = sKV + SMEM_KV_FLOATS;       // [QT] 1/rowsum

    const int tid  = threadIdx.x;
    const int bh   = blockIdx.y;
    const int q0   = blockIdx.x * QT;
    const int kind = g_mask_kind;
    const float scale = 0.125f;               // 1/sqrt(64)

    const float* Qp = Q + ((size_t)bh * Sn + q0) * Dn;
    const float* Kp = K + (size_t)bh * Sn * Dn;
    const float* Vp = V + (size_t)bh * Sn * Dn;

    // ---- load Q tile, transposed: sQt[d*QPAD + q] = Q[q0+q][d] ----
    for (int idx = tid; idx < QT * Dn; idx += NTHREADS) {
        int d = idx & (Dn - 1);
        int q = idx >> 6;
        sQt[d * QPAD + q] = Qp[q * Dn + d];
    }

    // =======================  QK^T + mask  =======================
    const int kx = tid & 31;   // 32 groups * 4 k = 128
    const int qy = tid >> 5;   // 8 groups * 4 q = 32

    for (int kt = 0; kt < NKT; kt++) {
        __syncthreads();
        // load K tile transposed: sKV[d*KPAD + k] = K[kt*KT + k][d]
        const float* Kt = Kp + (size_t)kt * KT * Dn;
        for (int idx = tid; idx < KT * Dn; idx += NTHREADS) {
            int d = idx & (Dn - 1);
            int k = idx >> 6;
            sKV[d * KPAD + k] = Kt[idx];
        }
        __syncthreads();

        float acc[4][4];
#pragma unroll
        for (int i = 0; i < 4; i++)
#pragma unroll
            for (int j = 0; j < 4; j++) acc[i][j] = 0.f;

        const float* aq = sQt + 4 * qy;
        const float* bk = sKV + 4 * kx;
#pragma unroll 8
        for (int d = 0; d < Dn; d++) {
            float4 a = *(const float4*)(aq + d * QPAD);  // warp-broadcast
            float4 b = *(const float4*)(bk + d * KPAD);  // conflict-free
            acc[0][0] = fmaf(a.x, b.x, acc[0][0]);
            acc[0][1] = fmaf(a.x, b.y, acc[0][1]);
            acc[0][2] = fmaf(a.x, b.z, acc[0][2]);
            acc[0][3] = fmaf(a.x, b.w, acc[0][3]);
            acc[1][0] = fmaf(a.y, b.x, acc[1][0]);
            acc[1][1] = fmaf(a.y, b.y, acc[1][1]);
            acc[1][2] = fmaf(a.y, b.z, acc[1][2]);
            acc[1][3] = fmaf(a.y, b.w, acc[1][3]);
            acc[2][0] = fmaf(a.z, b.x, acc[2][0]);
            acc[2][1] = fmaf(a.z, b.y, acc[2][1]);
            acc[2][2] = fmaf(a.z, b.z, acc[2][2]);
            acc[2][3] = fmaf(a.z, b.w, acc[2][3]);
            acc[3][0] = fmaf(a.w, b.x, acc[3][0]);
            acc[3][1] = fmaf(a.w, b.y, acc[3][1]);
            acc[3][2] = fmaf(a.w, b.z, acc[3][2]);
            acc[3][3] = fmaf(a.w, b.w, acc[3][3]);
        }

        // scale + mask + store to sS
        const int c = kt * KT + 4 * kx;
#pragma unroll
        for (int i = 0; i < 4; i++) {
            const int r = 4 * qy + i;
            const size_t mbase = ((size_t)bh * Sn + (q0 + r)) * (size_t)Sn + c;
            int m0, m1, m2, m3;
            if (kind == 0) {
                int4 mi = *(const int4*)((const int*)mask + mbase);
                m0 = mi.x; m1 = mi.y; m2 = mi.z; m3 = mi.w;
            } else if (kind == 1) {
                unsigned mw = *(const unsigned*)((const uint8_t*)mask + mbase);
                m0 = (int)(mw & 0xFFu);        m1 = (int)(mw & 0xFF00u);
                m2 = (int)(mw & 0xFF0000u);    m3 = (int)(mw & 0xFF000000u);
            } else if (kind == 2) {
                float4 mf = *(const float4*)((const float*)mask + mbase);
                m0 = (mf.x != 0.f); m1 = (mf.y != 0.f);
                m2 = (mf.z != 0.f); m3 = (mf.w != 0.f);
            } else {
                ushort4 mh = *(const ushort4*)((const uint16_t*)mask + mbase);
                m0 = mh.x; m1 = mh.y; m2 = mh.z; m3 = mh.w;
            }
            float4 v;
            v.x = m0 ? -1e9f : acc[i][0] * scale;
            v.y = m1 ? -1e9f : acc[i][1] * scale;
            v.z = m2 ? -1e9f : acc[i][2] * scale;
            v.w = m3 ? -1e9f : acc[i][3] * scale;
            *(float4*)(sS + r * Sn + c) = v;
        }
    }
    __syncthreads();

    // =======================  softmax  =======================
    {
        const int lane = tid & 31;
        const int w    = tid >> 5;
#pragma unroll
        for (int rr = 0; rr < 4; rr++) {
            const int r = 4 * w + rr;
            float* row = sS + r * Sn;
            float mx = -3.4e38f;
#pragma unroll
            for (int c8 = 0; c8 < Sn / 128; c8++) {
                float4 x = *(const float4*)(row + c8 * 128 + lane * 4);
                mx = fmaxf(mx, fmaxf(fmaxf(x.x, x.y), fmaxf(x.z, x.w)));
            }
#pragma unroll
            for (int o = 16; o; o >>= 1)
                mx = fmaxf(mx, __shfl_xor_sync(0xFFFFFFFFu, mx, o));
            float sum = 0.f;
#pragma unroll
            for (int c8 = 0; c8 < Sn / 128; c8++) {
                float4 x = *(float4*)(row + c8 * 128 + lane * 4);
                x.x = expf(x.x - mx);
                x.y = expf(x.y - mx);
                x.z = expf(x.z - mx);
                x.w = expf(x.w - mx);
                sum += (x.x + x.y) + (x.z + x.w);
                *(float4*)(row + c8 * 128 + lane * 4) = x;
            }
#pragma unroll
            for (int o = 16; o; o >>= 1)
                sum += __shfl_xor_sync(0xFFFFFFFFu, sum, o);
            if (lane == 0) sInv[r] = 1.0f / sum;
        }
    }
    __syncthreads();

    // =======================  write attn (normalized)  =======================
    {
        float* ao = attn_out + ((size_t)bh * Sn + q0) * (size_t)Sn;
        for (int idx = tid; idx < QT * Sn / 4; idx += NTHREADS) {
            const int r = idx >> 8;            // (idx*4)/1024
            const float inv = sInv[r];
            float4 x = *(const float4*)(sS + (size_t)idx * 4);
            x.x *= inv; x.y *= inv; x.z *= inv; x.w *= inv;
            *(float4*)(ao + (size_t)idx * 4) = x;   // rows contiguous in gmem
        }
    }

    // =======================  context = attn @ V  =======================
    const int dx  = tid & 15;   // 16 groups * 4 d = 64
    const int qy2 = tid >> 4;   // 16 groups * 2 q = 32
    float cacc[2][4];
#pragma unroll
    for (int i = 0; i < 2; i++)
#pragma unroll
        for (int j = 0; j < 4; j++) cacc[i][j] = 0.f;

    for (int kt = 0; kt < NKT; kt++) {
        __syncthreads();
        const float* Vt = Vp + (size_t)kt * KT * Dn;
        for (int idx = tid; idx < KT * Dn; idx += NTHREADS)
            sKV[idx] = Vt[idx];                 // natural [k][d], conflict-free
        __syncthreads();

        const float* a0 = sS + (2 * qy2) * Sn + kt * KT;
        const float* a1 = a0 + Sn;
        const float* bv = sKV + 4 * dx;
#pragma unroll 4
        for (int k = 0; k < KT; k++) {
            const float x0 = a0[k];
            const float x1 = a1[k];
            float4 b = *(const float4*)(bv + k * Dn);
            cacc[0][0] = fmaf(x0, b.x, cacc[0][0]);
            cacc[0][1] = fmaf(x0, b.y, cacc[0][1]);
            cacc[0][2] = fmaf(x0, b.z, cacc[0][2]);
            cacc[0][3] = fmaf(x0, b.w, cacc[0][3]);
            cacc[1][0] = fmaf(x1, b.x, cacc[1][0]);
            cacc[1][1] = fmaf(x1, b.y, cacc[1][1]);
            cacc[1][2] = fmaf(x1, b.z, cacc[1][2]);
            cacc[1][3] = fmaf(x1, b.w, cacc[1][3]);
        }
    }

    // write context (scaled by 1/rowsum)
    {
        float* co = ctx_out + ((size_t)bh * Sn + q0) * Dn;
#pragma unroll
        for (int i = 0; i < 2; i++) {
            const int r = 2 * qy2 + i;
            const float inv = sInv[r];
            float4 v;
            v.x = cacc[i][0] * inv;
            v.y = cacc[i][1] * inv;
            v.z = cacc[i][2] * inv;
            v.w = cacc[i][3] * inv;
            *(float4*)(co + (size_t)r * Dn + 4 * dx) = v;
        }
    }
}

extern "C" void kernel_launch(void* const* d_in, const int* in_sizes, int n_in,
                              void* d_out, int out_size) {
    const float* Q = (const float*)d_in[0];
    const float* K = (const float*)d_in[1];
    const float* V = (const float*)d_in[2];
    const void*  M = d_in[3];

    float* ctx  = (float*)d_out;                       // context first (return order)
    float* attn = ctx + (size_t)BHn * Sn * Dn;         // then attn

    // classify mask dtype on device (deterministic, graph-capturable)
    detect_mask_kind_kernel<<<1, 256>>>((const unsigned int*)M);

    cudaFuncSetAttribute(sdpa_fused_kernel,
                         cudaFuncAttributeMaxDynamicSharedMemorySize, SMEM_BYTES);
    dim3 grid(Sn / QT, BHn);
    sdpa_fused_kernel<<<grid, NTHREADS, SMEM_BYTES>>>(Q, K, V, M, ctx, attn);
}

// round 17
// speedup vs baseline: 1.0224x; 1.0224x over previous
#include <cuda_runtime.h>
#include <stdint.h>

// Problem shape (fixed for this problem instance)
#define Bn 8
#define Hn 12
#define Sn 1024
#define Dn 64
#define BHn (Bn*Hn)

#define QT 32            // query rows per block
#define KT 128           // k columns per score tile
#define NKT (Sn/KT)      // 8
#define NTHREADS 256

#define QPAD 40          // padded stride for transposed Q tile (mult of 4 words)
#define KPAD 136         // padded stride for transposed K tile (mult of 4 words)

#define SMEM_S_FLOATS   (QT*Sn)                 // 32768
#define SMEM_Q_FLOATS   (Dn*QPAD)               // 2560
#define SMEM_KV_FLOATS  ((Dn*KPAD > KT*Dn) ? (Dn*KPAD) : (KT*Dn))  // 8704
#define SMEM_TOTAL_FLOATS (SMEM_S_FLOATS + SMEM_Q_FLOATS + SMEM_KV_FLOATS + QT)
#define SMEM_BYTES (SMEM_TOTAL_FLOATS * 4)

// mask dtype classification result: 0=int32, 1=uint8/bool, 2=float32, 3=bfloat16
__device__ int g_mask_kind;

__global__ void detect_mask_kind_kernel(const unsigned int* __restrict__ mw) {
    int oi = 1, ou = 1, of = 1, ob = 1;
#pragma unroll
    for (int i = 0; i < 4; i++) {
        unsigned x = mw[threadIdx.x + i * 256];
        oi &= (x <= 1u);                                   // int32 words 0/1
        ou &= ((x & 0xFEFEFEFEu) == 0u);                   // every byte 0/1
        of &= (x == 0u || x == 0x3F800000u);               // fp32 0.0/1.0
        unsigned lo = x & 0xFFFFu, hi = x >> 16;
        ob &= ((lo == 0u || lo == 0x3F80u) && (hi == 0u || hi == 0x3F80u)); // bf16
    }
    oi = __syncthreads_and(oi);
    ou = __syncthreads_and(ou);
    of = __syncthreads_and(of);
    ob = __syncthreads_and(ob);
    if (threadIdx.x == 0)
        g_mask_kind = oi ? 0 : (ou ? 1 : (of ? 2 : (ob ? 3 : 1)));
}

__global__ __launch_bounds__(NTHREADS, 1)
void sdpa_fused_kernel(const float* __restrict__ Q,
                       const float* __restrict__ K,
                       const float* __restrict__ V,
                       const void*  __restrict__ mask,
                       float* __restrict__ ctx_out,
                       float* __restrict__ attn_out)
{
    extern __shared__ float sm[];
    float* sS   = sm;                         // [QT][Sn] scores / exp values
    float* sQt  = sS  + SMEM_S_FLOATS;        // [Dn][QPAD] transposed Q tile
    float* sKV  = sQt + SMEM_Q_FLOATS;        // K tile transposed / V tile natural
    float* sInv = sKV + SMEM_KV_FLOATS;       // [QT] 1/rowsum

    const int tid  = threadIdx.x;
    const int bh   = blockIdx.y;
    const int q0   = blockIdx.x * QT;
    const int kind = g_mask_kind;
    const float scale = 0.125f;               // 1/sqrt(64)

    const float* Qp = Q + ((size_t)bh * Sn + q0) * Dn;
    const float* Kp = K + (size_t)bh * Sn * Dn;
    const float* Vp = V + (size_t)bh * Sn * Dn;

    // ---- load Q tile, transposed: sQt[d*QPAD + q] = Q[q0+q][d] ----
    for (int idx = tid; idx < QT * Dn; idx += NTHREADS) {
        int d = idx & (Dn - 1);
        int q = idx >> 6;
        sQt[d * QPAD + q] = Qp[q * Dn + d];
    }

    // =======================  QK^T + mask  =======================
    const int kx = tid & 31;   // 32 groups * 4 k = 128
    const int qy = tid >> 5;   // 8 groups * 4 q = 32

    for (int kt = 0; kt < NKT; kt++) {
        __syncthreads();
        // load K tile transposed: sKV[d*KPAD + k] = K[kt*KT + k][d]
        const float* Kt = Kp + (size_t)kt * KT * Dn;
        for (int idx = tid; idx < KT * Dn; idx += NTHREADS) {
            int d = idx & (Dn - 1);
            int k = idx >> 6;
            sKV[d * KPAD + k] = Kt[idx];
        }
        __syncthreads();

        float acc[4][4];
#pragma unroll
        for (int i = 0; i < 4; i++)
#pragma unroll
            for (int j = 0; j < 4; j++) acc[i][j] = 0.f;

        const float* aq = sQt + 4 * qy;
        const float* bk = sKV + 4 * kx;
#pragma unroll 8
        for (int d = 0; d < Dn; d++) {
            float4 a = *(const float4*)(aq + d * QPAD);  // warp-broadcast
            float4 b = *(const float4*)(bk + d * KPAD);  // conflict-free
            acc[0][0] = fmaf(a.x, b.x, acc[0][0]);
            acc[0][1] = fmaf(a.x, b.y, acc[0][1]);
            acc[0][2] = fmaf(a.x, b.z, acc[0][2]);
            acc[0][3] = fmaf(a.x, b.w, acc[0][3]);
            acc[1][0] = fmaf(a.y, b.x, acc[1][0]);
            acc[1][1] = fmaf(a.y, b.y, acc[1][1]);
            acc[1][2] = fmaf(a.y, b.z, acc[1][2]);
            acc[1][3] = fmaf(a.y, b.w, acc[1][3]);
            acc[2][0] = fmaf(a.z, b.x, acc[2][0]);
            acc[2][1] = fmaf(a.z, b.y, acc[2][1]);
            acc[2][2] = fmaf(a.z, b.z, acc[2][2]);
            acc[2][3] = fmaf(a.z, b.w, acc[2][3]);
            acc[3][0] = fmaf(a.w, b.x, acc[3][0]);
            acc[3][1] = fmaf(a.w, b.y, acc[3][1]);
            acc[3][2] = fmaf(a.w, b.z, acc[3][2]);
            acc[3][3] = fmaf(a.w, b.w, acc[3][3]);
        }

        // scale + mask + store to sS
        const int c = kt * KT + 4 * kx;
#pragma unroll
        for (int i = 0; i < 4; i++) {
            const int r = 4 * qy + i;
            const size_t mbase = ((size_t)bh * Sn + (q0 + r)) * (size_t)Sn + c;
            int m0, m1, m2, m3;
            if (kind == 0) {
                int4 mi = *(const int4*)((const int*)mask + mbase);
                m0 = mi.x; m1 = mi.y; m2 = mi.z; m3 = mi.w;
            } else if (kind == 1) {
                unsigned mw = *(const unsigned*)((const uint8_t*)mask + mbase);
                m0 = (int)(mw & 0xFFu);        m1 = (int)(mw & 0xFF00u);
                m2 = (int)(mw & 0xFF0000u);    m3 = (int)(mw & 0xFF000000u);
            } else if (kind == 2) {
                float4 mf = *(const float4*)((const float*)mask + mbase);
                m0 = (mf.x != 0.f); m1 = (mf.y != 0.f);
                m2 = (mf.z != 0.f); m3 = (mf.w != 0.f);
            } else {
                ushort4 mh = *(const ushort4*)((const uint16_t*)mask + mbase);
                m0 = mh.x; m1 = mh.y; m2 = mh.z; m3 = mh.w;
            }
            float4 v;
            v.x = m0 ? -1e9f : acc[i][0] * scale;
            v.y = m1 ? -1e9f : acc[i][1] * scale;
            v.z = m2 ? -1e9f : acc[i][2] * scale;
            v.w = m3 ? -1e9f : acc[i][3] * scale;
            *(float4*)(sS + r * Sn + c) = v;
        }
    }
    __syncthreads();

    // =======================  softmax  =======================
    {
        const int lane = tid & 31;
        const int w    = tid >> 5;
#pragma unroll
        for (int rr = 0; rr < 4; rr++) {
            const int r = 4 * w + rr;
            float* row = sS + r * Sn;
            float mx = -3.4e38f;
#pragma unroll
            for (int c8 = 0; c8 < Sn / 128; c8++) {
                float4 x = *(const float4*)(row + c8 * 128 + lane * 4);
                mx = fmaxf(mx, fmaxf(fmaxf(x.x, x.y), fmaxf(x.z, x.w)));
            }
#pragma unroll
            for (int o = 16; o; o >>= 1)
                mx = fmaxf(mx, __shfl_xor_sync(0xFFFFFFFFu, mx, o));
            float sum = 0.f;
#pragma unroll
            for (int c8 = 0; c8 < Sn / 128; c8++) {
                float4 x = *(float4*)(row + c8 * 128 + lane * 4);
                x.x = expf(x.x - mx);
                x.y = expf(x.y - mx);
                x.z = expf(x.z - mx);
                x.w = expf(x.w - mx);
                sum += (x.x + x.y) + (x.z + x.w);
                *(float4*)(row + c8 * 128 + lane * 4) = x;
            }
#pragma unroll
            for (int o = 16; o; o >>= 1)
                sum += __shfl_xor_sync(0xFFFFFFFFu, sum, o);
            if (lane == 0) sInv[r] = 1.0f / sum;
        }
    }
    __syncthreads();

    // =======================  write attn (normalized)  =======================
    {
        float* ao = attn_out + ((size_t)bh * Sn + q0) * (size_t)Sn;
        for (int idx = tid; idx < QT * Sn / 4; idx += NTHREADS) {
            const int r = idx >> 8;            // (idx*4)/1024
            const float inv = sInv[r];
            float4 x = *(const float4*)(sS + (size_t)idx * 4);
            x.x *= inv; x.y *= inv; x.z *= inv; x.w *= inv;
            *(float4*)(ao + (size_t)idx * 4) = x;   // rows contiguous in gmem
        }
    }

    // =======================  context = attn @ V  =======================
    const int dx  = tid & 15;   // 16 groups * 4 d = 64
    const int qy2 = tid >> 4;   // 16 groups * 2 q = 32
    float cacc[2][4];
#pragma unroll
    for (int i = 0; i < 2; i++)
#pragma unroll
        for (int j = 0; j < 4; j++) cacc[i][j] = 0.f;

    for (int kt = 0; kt < NKT; kt++) {
        __syncthreads();
        const float* Vt = Vp + (size_t)kt * KT * Dn;
        for (int idx = tid; idx < KT * Dn; idx += NTHREADS)
            sKV[idx] = Vt[idx];                 // natural [k][d], conflict-free
        __syncthreads();

        const float* a0 = sS + (2 * qy2) * Sn + kt * KT;
        const float* a1 = a0 + Sn;
        const float* bv = sKV + 4 * dx;
#pragma unroll 4
        for (int k = 0; k < KT; k++) {
            const float x0 = a0[k];
            const float x1 = a1[k];
            float4 b = *(const float4*)(bv + k * Dn);
            cacc[0][0] = fmaf(x0, b.x, cacc[0][0]);
            cacc[0][1] = fmaf(x0, b.y, cacc[0][1]);
            cacc[0][2] = fmaf(x0, b.z, cacc[0][2]);
            cacc[0][3] = fmaf(x0, b.w, cacc[0][3]);
            cacc[1][0] = fmaf(x1, b.x, cacc[1][0]);
            cacc[1][1] = fmaf(x1, b.y, cacc[1][1]);
            cacc[1][2] = fmaf(x1, b.z, cacc[1][2]);
            cacc[1][3] = fmaf(x1, b.w, cacc[1][3]);
        }
    }

    // write context (scaled by 1/rowsum)
    {
        float* co = ctx_out + ((size_t)bh * Sn + q0) * Dn;
#pragma unroll
        for (int i = 0; i < 2; i++) {
            const int r = 2 * qy2 + i;
            const float inv = sInv[r];
            float4 v;
            v.x = cacc[i][0] * inv;
            v.y = cacc[i][1] * inv;
            v.z = cacc[i][2] * inv;
            v.w = cacc[i][3] * inv;
            *(float4*)(co + (size_t)r * Dn + 4 * dx) = v;
        }
    }
}

extern "C" void kernel_launch(void* const* d_in, const int* in_sizes, int n_in,
                              void* d_out, int out_size) {
    const float* Q = (const float*)d_in[0];
    const float* K = (const float*)d_in[1];
    const float* V = (const float*)d_in[2];
    const void*  M = d_in[3];

    float* ctx  = (float*)d_out;                       // context first (return order)
    float* attn = ctx + (size_t)BHn * Sn * Dn;         // then attn

    // classify mask dtype on device (deterministic, graph-capturable)
    detect_mask_kind_kernel<<<1, 256>>>((const unsigned int*)M);

    cudaFuncSetAttribute(sdpa_fused_kernel,
                         cudaFuncAttributeMaxDynamicSharedMemorySize, SMEM_BYTES);
    dim3 grid(Sn / QT, BHn);
    sdpa_fused_kernel<<<grid, NTHREADS, SMEM_BYTES>>>(Q, K, V, M, ctx, attn);
}